// round 12
// baseline (speedup 1.0000x reference)
#include <cuda_runtime.h>
#include <cstdint>

// Problem constants (fixed by the dataset instance)
#define BB    2
#define TT    2048
#define DD    1024
#define HH    16
#define HDIM  64
#define NQKV  (3*DD)          // 3072
#define MROWS (BB*TT)         // 4096
#define DW    (DD/2)          // u32 words per D-wide row (512)
#define QW    (NQKV/2)        // u32 words per qkv row (1536)

// Scratch (allocation-free rule: __device__ globals). All bf16x2-packed (u32).
__device__ uint32_t g_xh [(size_t)MROWS * DW], g_xl [(size_t)MROWS * DW];
__device__ uint32_t g_wqh[(size_t)NQKV  * DW], g_wql[(size_t)NQKV  * DW];
__device__ uint32_t g_woh[(size_t)DD    * DW], g_wol[(size_t)DD    * DW];
__device__ uint32_t g_qh [(size_t)MROWS * QW], g_ql [(size_t)MROWS * QW];
__device__ uint32_t g_ah [(size_t)MROWS * DW], g_al [(size_t)MROWS * DW];

// ===========================================================================
// Baseline-PTX helpers (no sm_103a-gated instructions).
// ===========================================================================
__device__ __forceinline__ uint32_t smem_u32(const void* p) {
    uint32_t a;
    asm("{ .reg .u64 t; cvta.to.shared.u64 t, %1; cvt.u32.u64 %0, t; }"
        : "=r"(a) : "l"(p));
    return a;
}

__device__ __forceinline__ void ldm_x4(uint32_t r[4], uint32_t addr) {
    asm volatile("ldmatrix.sync.aligned.m8n8.x4.shared.b16 {%0,%1,%2,%3}, [%4];"
                 : "=r"(r[0]), "=r"(r[1]), "=r"(r[2]), "=r"(r[3]) : "r"(addr));
}

__device__ __forceinline__ void ldm_x4_t(uint32_t r[4], uint32_t addr) {
    asm volatile("ldmatrix.sync.aligned.m8n8.x4.trans.shared.b16 {%0,%1,%2,%3}, [%4];"
                 : "=r"(r[0]), "=r"(r[1]), "=r"(r[2]), "=r"(r[3]) : "r"(addr));
}

__device__ __forceinline__ void mma_bf16(float c[4], const uint32_t a[4],
                                         uint32_t b0, uint32_t b1) {
    asm volatile(
        "mma.sync.aligned.m16n8k16.row.col.f32.bf16.bf16.f32 "
        "{%0,%1,%2,%3}, {%4,%5,%6,%7}, {%8,%9}, {%0,%1,%2,%3};"
        : "+f"(c[0]), "+f"(c[1]), "+f"(c[2]), "+f"(c[3])
        : "r"(a[0]), "r"(a[1]), "r"(a[2]), "r"(a[3]), "r"(b0), "r"(b1));
}

// pack two floats into bf16x2: first arg -> LOW 16 bits (even-k element)
__device__ __forceinline__ uint32_t packbf(float lo, float hi) {
    uint32_t r;
    asm("cvt.rn.bf16x2.f32 %0, %1, %2;" : "=r"(r) : "f"(hi), "f"(lo));
    return r;
}

__device__ __forceinline__ uint32_t lo_pack(uint32_t hpk, float f0, float f1) {
    float h0 = __uint_as_float(hpk << 16);
    float h1 = __uint_as_float(hpk & 0xffff0000u);
    return packbf(f0 - h0, f1 - h1);
}

__device__ __forceinline__ void split4(float4 v, uint2& h, uint2& l) {
    h.x = packbf(v.x, v.y);
    h.y = packbf(v.z, v.w);
    l.x = lo_pack(h.x, v.x, v.y);
    l.y = lo_pack(h.y, v.z, v.w);
}

__device__ __forceinline__ void cp16(uint32_t dst, const uint32_t* src) {
    asm volatile("cp.async.cg.shared.global [%0], [%1], 16;"
                 :: "r"(dst), "l"(src) : "memory");
}
__device__ __forceinline__ void cp_commit() {
    asm volatile("cp.async.commit_group;" ::: "memory");
}
__device__ __forceinline__ void cp_wait0() {
    asm volatile("cp.async.wait_group 0;" ::: "memory");
}

// ===========================================================================
// Pre-pass: split fp32 matrix into bf16 hi/lo (packed u32 pairs).
// ===========================================================================
__global__ void split_f32(const float4* __restrict__ src, uint2* __restrict__ h,
                          uint2* __restrict__ l, int n4)
{
    int i = blockIdx.x * 256 + threadIdx.x;
    if (i < n4) {
        uint2 hh, ll;
        split4(src[i], hh, ll);
        h[i] = hh;
        l[i] = ll;
    }
}

// ===========================================================================
// bf16x3 tensor-core GEMM, cp.async 2-stage pipeline, pre-split inputs.
// C[M,N] = A[M,K] @ B[N,K]^T + bias[N]; A,B given as hi/lo bf16 (u32-packed).
// CTA 128x128, 8 warps (warp tile 64x32), K-step 32, fp32 accumulate.
// Inner loop ordered so A-lo ldmatrix latency is covered by term-2 MMAs.
// split_out=1: write C as hi/lo bf16. split_out=0: fp32 C32.
// ===========================================================================
#define RS 80
#define TILE_B (128 * RS)          // 10240
#define STAGE_B (4 * TILE_B)       // Ah,Al,Bh,Bl
#define GK_SMEM (2 * STAGE_B + 128)

__global__ void __launch_bounds__(256, 2)
bf16x3_gemm_async(const uint32_t* __restrict__ Ah, const uint32_t* __restrict__ Al,
                  const uint32_t* __restrict__ Bh, const uint32_t* __restrict__ Bl,
                  const float* __restrict__ bias,
                  float* __restrict__ C32,
                  uint32_t* __restrict__ Ch, uint32_t* __restrict__ Cl,
                  int M, int N, int K, int split_out)
{
    extern __shared__ char smem[];
    const uint32_t sb = (smem_u32(smem) + 127) & ~127u;

    const int tid  = threadIdx.x;
    const int lane = tid & 31;
    const int wid  = tid >> 5;
    const int wm   = wid & 1;
    const int wn   = wid >> 1;
    const int m0   = blockIdx.y * 128;
    const int n0   = blockIdx.x * 128;
    const int Kw   = K >> 1;          // u32 words per row

    float acc[4][4][4];
    #pragma unroll
    for (int i = 0; i < 4; i++)
        #pragma unroll
        for (int j = 0; j < 4; j++)
            #pragma unroll
            for (int q = 0; q < 4; q++) acc[i][j][q] = 0.f;

    // Each thread copies one 32B half-row per tile per stage.
    const int row  = tid >> 1;
    const int half = tid & 1;
    const uint32_t soff = (uint32_t)(row * RS + half * 32);

    const uint32_t* gAh = Ah + (size_t)(m0 + row) * Kw + half * 8;
    const uint32_t* gAl = Al + (size_t)(m0 + row) * Kw + half * 8;
    const uint32_t* gBh = Bh + (size_t)(n0 + row) * Kw + half * 8;
    const uint32_t* gBl = Bl + (size_t)(n0 + row) * Kw + half * 8;

    const uint32_t aLane = (uint32_t)((wm * 64 + (lane & 15)) * RS
                                      + (lane >> 4) * 16);
    const uint32_t bLane = (uint32_t)((wn * 32 + ((lane >> 4) & 1) * 8
                                       + (lane & 7)) * RS
                                      + ((lane >> 3) & 1) * 16);

    const int NIT = K / 32;

    // issue stage 0
    {
        const uint32_t d = sb + soff;
        cp16(d,                  gAh); cp16(d + 16,              gAh + 4);
        cp16(d + TILE_B,         gAl); cp16(d + TILE_B + 16,     gAl + 4);
        cp16(d + 2 * TILE_B,     gBh); cp16(d + 2 * TILE_B + 16, gBh + 4);
        cp16(d + 3 * TILE_B,     gBl); cp16(d + 3 * TILE_B + 16, gBl + 4);
        cp_commit();
    }

    for (int it = 0; it < NIT; ++it) {
        cp_wait0();
        __syncthreads();

        if (it + 1 < NIT) {
            const uint32_t d  = sb + (uint32_t)(((it + 1) & 1) * STAGE_B) + soff;
            const int      ko = (it + 1) * 16;   // u32 offset along K
            cp16(d,                  gAh + ko); cp16(d + 16,              gAh + ko + 4);
            cp16(d + TILE_B,         gAl + ko); cp16(d + TILE_B + 16,     gAl + ko + 4);
            cp16(d + 2 * TILE_B,     gBh + ko); cp16(d + 2 * TILE_B + 16, gBh + ko + 4);
            cp16(d + 3 * TILE_B,     gBl + ko); cp16(d + 3 * TILE_B + 16, gBl + ko + 4);
            cp_commit();
        }

        const uint32_t cur   = sb + (uint32_t)((it & 1) * STAGE_B);
        const uint32_t aAddr = cur + aLane;
        const uint32_t bAddr = cur + 2 * TILE_B + bLane;

        #pragma unroll
        for (int ks = 0; ks < 2; ks++) {
            const uint32_t ko = (uint32_t)(ks * 32);

            uint32_t afh[4][4], afl[4][4], bh[4][2], bl[4][2];
            #pragma unroll
            for (int mi = 0; mi < 4; mi++)
                ldm_x4(afh[mi], aAddr + (uint32_t)(mi * 16 * RS) + ko);
            #pragma unroll
            for (int j2 = 0; j2 < 2; j2++) {
                uint32_t t[4];
                ldm_x4(t, bAddr + (uint32_t)(j2 * 16 * RS) + ko);
                bh[2*j2][0] = t[0]; bh[2*j2][1] = t[1];
                bh[2*j2+1][0] = t[2]; bh[2*j2+1][1] = t[3];
                ldm_x4(t, bAddr + (uint32_t)(TILE_B + j2 * 16 * RS) + ko);
                bl[2*j2][0] = t[0]; bl[2*j2][1] = t[1];
                bl[2*j2+1][0] = t[2]; bl[2*j2+1][1] = t[3];
            }

            // term 1: Ah x Bh
            #pragma unroll
            for (int mi = 0; mi < 4; mi++)
                #pragma unroll
                for (int nj = 0; nj < 4; nj++)
                    mma_bf16(acc[mi][nj], afh[mi], bh[nj][0], bh[nj][1]);
            // load A-lo now; term-2 MMAs below cover its latency
            #pragma unroll
            for (int mi = 0; mi < 4; mi++)
                ldm_x4(afl[mi], aAddr + (uint32_t)(TILE_B + mi * 16 * RS) + ko);
            // term 2: Ah x Bl
            #pragma unroll
            for (int mi = 0; mi < 4; mi++)
                #pragma unroll
                for (int nj = 0; nj < 4; nj++)
                    mma_bf16(acc[mi][nj], afh[mi], bl[nj][0], bl[nj][1]);
            // term 3: Al x Bh
            #pragma unroll
            for (int mi = 0; mi < 4; mi++)
                #pragma unroll
                for (int nj = 0; nj < 4; nj++)
                    mma_bf16(acc[mi][nj], afl[mi], bh[nj][0], bh[nj][1]);
        }
    }

    const int g = lane >> 2;
    const int s = lane & 3;
    if (split_out) {
        const int Nw = N >> 1;
        #pragma unroll
        for (int mi = 0; mi < 4; mi++) {
            const int mrow = m0 + wm * 64 + mi * 16 + g;
            #pragma unroll
            for (int nj = 0; nj < 4; nj++) {
                const int ncol = n0 + wn * 32 + nj * 8 + s * 2;
                float2 bv = *(const float2*)(bias + ncol);
                float v0 = acc[mi][nj][0] + bv.x;
                float v1 = acc[mi][nj][1] + bv.y;
                float v2 = acc[mi][nj][2] + bv.x;
                float v3 = acc[mi][nj][3] + bv.y;
                uint32_t hw0 = packbf(v0, v1);
                uint32_t hw1 = packbf(v2, v3);
                const size_t i0 = (size_t)mrow * Nw + (ncol >> 1);
                const size_t i1 = (size_t)(mrow + 8) * Nw + (ncol >> 1);
                Ch[i0] = hw0;  Cl[i0] = lo_pack(hw0, v0, v1);
                Ch[i1] = hw1;  Cl[i1] = lo_pack(hw1, v2, v3);
            }
        }
    } else {
        #pragma unroll
        for (int mi = 0; mi < 4; mi++) {
            const int mrow = m0 + wm * 64 + mi * 16 + g;
            #pragma unroll
            for (int nj = 0; nj < 4; nj++) {
                const int ncol = n0 + wn * 32 + nj * 8 + s * 2;
                float2 bv = *(const float2*)(bias + ncol);
                float2 o0, o1;
                o0.x = acc[mi][nj][0] + bv.x;  o0.y = acc[mi][nj][1] + bv.y;
                o1.x = acc[mi][nj][2] + bv.x;  o1.y = acc[mi][nj][3] + bv.y;
                *(float2*)(C32 + (size_t)mrow * N + ncol)       = o0;
                *(float2*)(C32 + (size_t)(mrow + 8) * N + ncol) = o1;
            }
        }
    }
}

// ===========================================================================
// Tensor-core flash attention (causal), pre-split bf16, cp.async K/V pipe.
// NOW: 128-row Q tile per CTA, 256 threads / 8 warps (warp = 16 q-rows).
// Halves CTA count + K/V gmem traffic; 16 warps/SM at 2 CTA/SM.
// Causal mask applied for the last two key blocks (j >= 2I).
// ===========================================================================
#define AT_RS    144
#define AT_T64   (64 * AT_RS)                 // 9216  (one 64-row K or V tile)
#define AT_QROWS 128
#define AT_QT    (AT_QROWS * AT_RS)           // 18432 (128-row Q tile)
#define AT_QH    0
#define AT_QL    AT_QT
#define AT_KV0   (2 * AT_QT)                  // stage s at AT_KV0 + s*4*AT_T64
#define AT_SMEM  (2 * AT_QT + 2 * 4 * AT_T64 + 128)   // 110720

__global__ void __launch_bounds__(256, 2)
flash_attn_mma(const uint32_t* __restrict__ qh, const uint32_t* __restrict__ ql,
               uint32_t* __restrict__ ah, uint32_t* __restrict__ al)
{
    extern __shared__ char smem[];
    const uint32_t sb = (smem_u32(smem) + 127) & ~127u;

    const int I    = (int)gridDim.x - 1 - (int)blockIdx.x;   // heavy first
    const int h    = blockIdx.y;
    const int b    = blockIdx.z;
    const int tid  = threadIdx.x;
    const int lane = tid & 31;
    const int w    = tid >> 5;          // 0..7, warp owns q-rows [w*16, w*16+16)
    const int jmax = 2 * I + 1;

    const uint32_t* baseh = qh + (size_t)b * TT * QW + h * 96;  // h*192 bf16
    const uint32_t* basel = ql + (size_t)b * TT * QW + h * 96;

    // Q: 128 rows x 8 chunks(16B) = 1024 chunks per tile (hi & lo)
    {
        #pragma unroll
        for (int itx = 0; itx < 4; itx++) {
            const int f = tid + itx * 256;
            const int r = f >> 3, c = f & 7;
            const size_t go = (size_t)(I * 128 + r) * QW + c * 4;
            const uint32_t off = (uint32_t)(r * AT_RS + c * 16);
            cp16(sb + AT_QH + off, baseh + go);
            cp16(sb + AT_QL + off, basel + go);
        }
    }
    auto issueKV = [&](int j, int stg) {
        const uint32_t st = sb + AT_KV0 + (uint32_t)(stg * 4 * AT_T64);
        #pragma unroll
        for (int itx = 0; itx < 2; itx++) {
            const int f = tid + itx * 256;
            const int r = f >> 3, c = f & 7;
            const size_t go = (size_t)(j * 64 + r) * QW + 32 + c * 4;  // K
            const uint32_t off = (uint32_t)(r * AT_RS + c * 16);
            cp16(st + off,              baseh + go);        // Kh
            cp16(st + AT_T64 + off,     basel + go);        // Kl
            cp16(st + 2 * AT_T64 + off, baseh + go + 32);   // Vh
            cp16(st + 3 * AT_T64 + off, basel + go + 32);   // Vl
        }
    };

    issueKV(0, 0);
    cp_commit();

    const int g = lane >> 2;
    const int s = lane & 3;

    const uint32_t aQ = sb + AT_QH +
        (uint32_t)((w * 16 + (lane & 15)) * AT_RS + (lane >> 4) * 16);
    const uint32_t kLane =
        (uint32_t)((((lane >> 4) & 1) * 8 + (lane & 7)) * AT_RS
                   + ((lane >> 3) & 1) * 16);
    const uint32_t vLane =
        (uint32_t)((((lane >> 3) & 1) * 8 + (lane & 7)) * AT_RS
                   + ((lane >> 4) & 1) * 16);

    float m0v = -1e30f, m1v = -1e30f, l0v = 0.f, l1v = 0.f;
    float o[8][4];
    #pragma unroll
    for (int nt = 0; nt < 8; nt++)
        #pragma unroll
        for (int q = 0; q < 4; q++) o[nt][q] = 0.f;

    const int qrow0 = I * 128 + w * 16 + g;

    for (int j = 0; j <= jmax; j++) {
        const int cur = j & 1;
        cp_wait0();
        __syncthreads();
        if (j < jmax) {
            issueKV(j + 1, cur ^ 1);
            cp_commit();
        }

        const uint32_t st = sb + AT_KV0 + (uint32_t)(cur * 4 * AT_T64);
        const uint32_t bK = st + kLane;
        const uint32_t bV = st + 2 * AT_T64 + vLane;

        // ---- S = Q @ K^T (3-term split, fp32 accum) ----
        float sacc[8][4];
        #pragma unroll
        for (int nt = 0; nt < 8; nt++)
            #pragma unroll
            for (int q = 0; q < 4; q++) sacc[nt][q] = 0.f;

        #pragma unroll
        for (int ks = 0; ks < 4; ks++) {
            const uint32_t ko = (uint32_t)(ks * 32);
            uint32_t qhf[4], qlf[4];
            ldm_x4(qhf, aQ + ko);
            ldm_x4(qlf, aQ + (uint32_t)AT_QT + ko);
            #pragma unroll
            for (int nb = 0; nb < 4; nb++) {
                uint32_t t[4], tl[4];
                ldm_x4(t,  bK + (uint32_t)(nb * 16 * AT_RS) + ko);
                ldm_x4(tl, bK + (uint32_t)(AT_T64 + nb * 16 * AT_RS) + ko);
                mma_bf16(sacc[2*nb],   qhf, t[0],  t[1]);
                mma_bf16(sacc[2*nb+1], qhf, t[2],  t[3]);
                mma_bf16(sacc[2*nb],   qhf, tl[0], tl[1]);
                mma_bf16(sacc[2*nb+1], qhf, tl[2], tl[3]);
                mma_bf16(sacc[2*nb],   qlf, t[0],  t[1]);
                mma_bf16(sacc[2*nb+1], qlf, t[2],  t[3]);
            }
        }

        // scale 1/sqrt(hd) = 0.125
        #pragma unroll
        for (int nt = 0; nt < 8; nt++) {
            sacc[nt][0] *= 0.125f; sacc[nt][1] *= 0.125f;
            sacc[nt][2] *= 0.125f; sacc[nt][3] *= 0.125f;
        }

        // ---- causal mask (last two key blocks of this Q tile) ----
        if (j >= 2 * I) {
            #pragma unroll
            for (int nt = 0; nt < 8; nt++) {
                const int col = j * 64 + nt * 8 + s * 2;
                if (col     > qrow0)     sacc[nt][0] = -1e30f;
                if (col + 1 > qrow0)     sacc[nt][1] = -1e30f;
                if (col     > qrow0 + 8) sacc[nt][2] = -1e30f;
                if (col + 1 > qrow0 + 8) sacc[nt][3] = -1e30f;
            }
        }

        // ---- online softmax on fragments ----
        float mx0 = -1e30f, mx1 = -1e30f;
        #pragma unroll
        for (int nt = 0; nt < 8; nt++) {
            mx0 = fmaxf(mx0, fmaxf(sacc[nt][0], sacc[nt][1]));
            mx1 = fmaxf(mx1, fmaxf(sacc[nt][2], sacc[nt][3]));
        }
        mx0 = fmaxf(mx0, __shfl_xor_sync(0xffffffffu, mx0, 1));
        mx0 = fmaxf(mx0, __shfl_xor_sync(0xffffffffu, mx0, 2));
        mx1 = fmaxf(mx1, __shfl_xor_sync(0xffffffffu, mx1, 1));
        mx1 = fmaxf(mx1, __shfl_xor_sync(0xffffffffu, mx1, 2));

        const float mn0 = fmaxf(m0v, mx0);
        const float mn1 = fmaxf(m1v, mx1);
        const float cr0 = __expf(m0v - mn0);
        const float cr1 = __expf(m1v - mn1);

        float rs0 = 0.f, rs1 = 0.f;
        #pragma unroll
        for (int nt = 0; nt < 8; nt++) {
            float p0 = __expf(sacc[nt][0] - mn0);
            float p1 = __expf(sacc[nt][1] - mn0);
            float p2 = __expf(sacc[nt][2] - mn1);
            float p3 = __expf(sacc[nt][3] - mn1);
            sacc[nt][0] = p0; sacc[nt][1] = p1;
            sacc[nt][2] = p2; sacc[nt][3] = p3;
            rs0 += p0 + p1;
            rs1 += p2 + p3;
        }
        rs0 += __shfl_xor_sync(0xffffffffu, rs0, 1);
        rs0 += __shfl_xor_sync(0xffffffffu, rs0, 2);
        rs1 += __shfl_xor_sync(0xffffffffu, rs1, 1);
        rs1 += __shfl_xor_sync(0xffffffffu, rs1, 2);

        l0v = l0v * cr0 + rs0;
        l1v = l1v * cr1 + rs1;
        m0v = mn0;
        m1v = mn1;
        #pragma unroll
        for (int nt = 0; nt < 8; nt++) {
            o[nt][0] *= cr0; o[nt][1] *= cr0;
            o[nt][2] *= cr1; o[nt][3] *= cr1;
        }

        // ---- O += P @ V (3-term; P from registers, V via ldmatrix.trans) ----
        #pragma unroll
        for (int ks = 0; ks < 4; ks++) {
            uint32_t ph[4], pl[4];
            ph[0] = packbf(sacc[2*ks][0],   sacc[2*ks][1]);
            ph[1] = packbf(sacc[2*ks][2],   sacc[2*ks][3]);
            ph[2] = packbf(sacc[2*ks+1][0], sacc[2*ks+1][1]);
            ph[3] = packbf(sacc[2*ks+1][2], sacc[2*ks+1][3]);
            pl[0] = lo_pack(ph[0], sacc[2*ks][0],   sacc[2*ks][1]);
            pl[1] = lo_pack(ph[1], sacc[2*ks][2],   sacc[2*ks][3]);
            pl[2] = lo_pack(ph[2], sacc[2*ks+1][0], sacc[2*ks+1][1]);
            pl[3] = lo_pack(ph[3], sacc[2*ks+1][2], sacc[2*ks+1][3]);

            const uint32_t krow = (uint32_t)(ks * 16 * AT_RS);
            #pragma unroll
            for (int nb = 0; nb < 4; nb++) {
                uint32_t t[4], tl[4];
                ldm_x4_t(t,  bV + krow + (uint32_t)(nb * 32));
                ldm_x4_t(tl, bV + (uint32_t)AT_T64 + krow + (uint32_t)(nb * 32));
                mma_bf16(o[2*nb],   ph, t[0],  t[1]);
                mma_bf16(o[2*nb+1], ph, t[2],  t[3]);
                mma_bf16(o[2*nb],   ph, tl[0], tl[1]);
                mma_bf16(o[2*nb+1], ph, tl[2], tl[3]);
                mma_bf16(o[2*nb],   pl, t[0],  t[1]);
                mma_bf16(o[2*nb+1], pl, t[2],  t[3]);
            }
        }
    }

    // ---- epilogue: normalize and write attn as hi/lo bf16 [B*T, D/2 u32] ----
    const float inv0 = 1.f / l0v;
    const float inv1 = 1.f / l1v;
    const size_t r0 = (size_t)b * TT + I * 128 + w * 16 + g;
    #pragma unroll
    for (int nt = 0; nt < 8; nt++) {
        const int colw = h * 32 + nt * 4 + s;   // u32 column
        float v0 = o[nt][0] * inv0, v1 = o[nt][1] * inv0;
        float v2 = o[nt][2] * inv1, v3 = o[nt][3] * inv1;
        uint32_t h0 = packbf(v0, v1);
        uint32_t h1 = packbf(v2, v3);
        ah[r0 * DW + colw]       = h0;
        al[r0 * DW + colw]       = lo_pack(h0, v0, v1);
        ah[(r0 + 8) * DW + colw] = h1;
        al[(r0 + 8) * DW + colw] = lo_pack(h1, v2, v3);
    }
}

// ===========================================================================
// Launch: splits -> qkv GEMM (split-out) -> flash (split-out) -> out GEMM.
// ===========================================================================
extern "C" void kernel_launch(void* const* d_in, const int* in_sizes, int n_in,
                              void* d_out, int out_size)
{
    const float* x    = (const float*)d_in[0];
    const float* Wqkv = (const float*)d_in[1];
    const float* bqkv = (const float*)d_in[2];
    const float* Wout = (const float*)d_in[3];
    const float* bout = (const float*)d_in[4];
    float*       out  = (float*)d_out;

    uint32_t *xh, *xl, *wqh, *wql, *woh, *wol, *qhp, *qlp, *ahp, *alp;
    cudaGetSymbolAddress((void**)&xh,  g_xh);
    cudaGetSymbolAddress((void**)&xl,  g_xl);
    cudaGetSymbolAddress((void**)&wqh, g_wqh);
    cudaGetSymbolAddress((void**)&wql, g_wql);
    cudaGetSymbolAddress((void**)&woh, g_woh);
    cudaGetSymbolAddress((void**)&wol, g_wol);
    cudaGetSymbolAddress((void**)&qhp, g_qh);
    cudaGetSymbolAddress((void**)&qlp, g_ql);
    cudaGetSymbolAddress((void**)&ahp, g_ah);
    cudaGetSymbolAddress((void**)&alp, g_al);

    cudaFuncSetAttribute(bf16x3_gemm_async,
                         cudaFuncAttributeMaxDynamicSharedMemorySize, GK_SMEM);
    cudaFuncSetAttribute(flash_attn_mma,
                         cudaFuncAttributeMaxDynamicSharedMemorySize, AT_SMEM);

    // 0) pre-split fp32 -> bf16 hi/lo
    {
        int n4;
        n4 = MROWS * DD / 4;
        split_f32<<<(n4 + 255) / 256, 256>>>((const float4*)x, (uint2*)xh, (uint2*)xl, n4);
        n4 = NQKV * DD / 4;
        split_f32<<<(n4 + 255) / 256, 256>>>((const float4*)Wqkv, (uint2*)wqh, (uint2*)wql, n4);
        n4 = DD * DD / 4;
        split_f32<<<(n4 + 255) / 256, 256>>>((const float4*)Wout, (uint2*)woh, (uint2*)wol, n4);
    }
    // 1) qkv = x @ Wqkv^T + bqkv -> hi/lo bf16
    {
        dim3 grid(NQKV / 128, MROWS / 128);   // (24, 32)
        bf16x3_gemm_async<<<grid, 256, GK_SMEM>>>(xh, xl, wqh, wql, bqkv,
                                                  nullptr, qhp, qlp,
                                                  MROWS, NQKV, DD, 1);
    }
    // 2) attention -> hi/lo bf16 (128-row Q tiles)
    {
        dim3 grid(TT / 128, HH, BB);          // (16, 16, 2)
        flash_attn_mma<<<grid, 256, AT_SMEM>>>(qhp, qlp, ahp, alp);
    }
    // 3) out = attn @ Wout^T + bout (fp32)
    {
        dim3 grid(DD / 128, MROWS / 128);     // (8, 32)
        bf16x3_gemm_async<<<grid, 256, GK_SMEM>>>(ahp, alp, woh, wol, bout,
                                                  out, nullptr, nullptr,
                                                  MROWS, DD, DD, 0);
    }
}

// round 13
// speedup vs baseline: 1.4599x; 1.4599x over previous
#include <cuda_runtime.h>
#include <cuda_fp16.h>
#include <cstdint>

// Problem constants (fixed by the dataset instance)
#define BB    2
#define TT    2048
#define DD    1024
#define HH    16
#define HDIM  64
#define NQKV  (3*DD)          // 3072
#define MROWS (BB*TT)         // 4096
#define DW    (DD/2)          // u32 words per D-wide row (512)
#define QW    (NQKV/2)        // u32 words per qkv row (1536)

// Scratch (allocation-free rule: __device__ globals). All fp16x2-packed (u32).
__device__ uint32_t g_xh [(size_t)MROWS * DW], g_xl [(size_t)MROWS * DW];
__device__ uint32_t g_wq [(size_t)NQKV  * DW];               // Wqkv single fp16
__device__ uint32_t g_wo [(size_t)DD    * DW];               // Wout  single fp16
__device__ uint32_t g_qh [(size_t)MROWS * QW], g_ql [(size_t)MROWS * QW];
__device__ uint32_t g_ah [(size_t)MROWS * DW], g_al [(size_t)MROWS * DW];

// ===========================================================================
// Baseline-PTX helpers (no sm_103a-gated instructions).
// ===========================================================================
__device__ __forceinline__ uint32_t smem_u32(const void* p) {
    uint32_t a;
    asm("{ .reg .u64 t; cvta.to.shared.u64 t, %1; cvt.u32.u64 %0, t; }"
        : "=r"(a) : "l"(p));
    return a;
}

__device__ __forceinline__ void ldm_x4(uint32_t r[4], uint32_t addr) {
    asm volatile("ldmatrix.sync.aligned.m8n8.x4.shared.b16 {%0,%1,%2,%3}, [%4];"
                 : "=r"(r[0]), "=r"(r[1]), "=r"(r[2]), "=r"(r[3]) : "r"(addr));
}

__device__ __forceinline__ void ldm_x4_t(uint32_t r[4], uint32_t addr) {
    asm volatile("ldmatrix.sync.aligned.m8n8.x4.trans.shared.b16 {%0,%1,%2,%3}, [%4];"
                 : "=r"(r[0]), "=r"(r[1]), "=r"(r[2]), "=r"(r[3]) : "r"(addr));
}

__device__ __forceinline__ void mma_f16(float c[4], const uint32_t a[4],
                                        uint32_t b0, uint32_t b1) {
    asm volatile(
        "mma.sync.aligned.m16n8k16.row.col.f32.f16.f16.f32 "
        "{%0,%1,%2,%3}, {%4,%5,%6,%7}, {%8,%9}, {%0,%1,%2,%3};"
        : "+f"(c[0]), "+f"(c[1]), "+f"(c[2]), "+f"(c[3])
        : "r"(a[0]), "r"(a[1]), "r"(a[2]), "r"(a[3]), "r"(b0), "r"(b1));
}

// pack two floats into f16x2: first arg -> LOW 16 bits (even-k element)
__device__ __forceinline__ uint32_t packh(float lo, float hi) {
    uint32_t r;
    asm("cvt.rn.f16x2.f32 %0, %1, %2;" : "=r"(r) : "f"(hi), "f"(lo));
    return r;
}

// residual (lo) pair for a given hi-pack
__device__ __forceinline__ uint32_t lo_packh(uint32_t hpk, float f0, float f1) {
    float h0 = __half2float(__ushort_as_half((unsigned short)(hpk & 0xffffu)));
    float h1 = __half2float(__ushort_as_half((unsigned short)(hpk >> 16)));
    return packh(f0 - h0, f1 - h1);
}

// split float4 (4 consecutive k) into hi-pair / lo-pair f16x2 words
__device__ __forceinline__ void split4h(float4 v, uint2& h, uint2& l) {
    h.x = packh(v.x, v.y);
    h.y = packh(v.z, v.w);
    l.x = lo_packh(h.x, v.x, v.y);
    l.y = lo_packh(h.y, v.z, v.w);
}

__device__ __forceinline__ void cp16(uint32_t dst, const uint32_t* src) {
    asm volatile("cp.async.cg.shared.global [%0], [%1], 16;"
                 :: "r"(dst), "l"(src) : "memory");
}
__device__ __forceinline__ void cp_commit() {
    asm volatile("cp.async.commit_group;" ::: "memory");
}
__device__ __forceinline__ void cp_wait0() {
    asm volatile("cp.async.wait_group 0;" ::: "memory");
}

// ===========================================================================
// Pre-passes: fp32 -> fp16 hi/lo split (activations), fp32 -> fp16 (weights)
// ===========================================================================
__global__ void split_f32h(const float4* __restrict__ src, uint2* __restrict__ h,
                           uint2* __restrict__ l, int n4)
{
    int i = blockIdx.x * 256 + threadIdx.x;
    if (i < n4) {
        uint2 hh, ll;
        split4h(src[i], hh, ll);
        h[i] = hh;
        l[i] = ll;
    }
}

__global__ void conv_f32h(const float4* __restrict__ src, uint2* __restrict__ h,
                          int n4)
{
    int i = blockIdx.x * 256 + threadIdx.x;
    if (i < n4) {
        float4 v = src[i];
        h[i] = make_uint2(packh(v.x, v.y), packh(v.z, v.w));
    }
}

// ===========================================================================
// fp16 asymmetric 2-term GEMM, cp.async 2-stage pipeline.
// C[M,N] = (Ah+Al)[M,K] @ B[N,K]^T + bias[N];  A hi/lo fp16, B single fp16.
// CTA 128x128, 8 warps (warp tile 64x32), K-step 32, fp32 accumulate.
// split_out=1: write C as hi/lo fp16. split_out=0: fp32 C32.
// ===========================================================================
#define RS 80
#define TILE_B (128 * RS)          // 10240
#define STAGE_B (3 * TILE_B)       // Ah, Al, B
#define GK_SMEM (2 * STAGE_B + 128)

__global__ void __launch_bounds__(256, 2)
fp16x2_gemm_async(const uint32_t* __restrict__ Ah, const uint32_t* __restrict__ Al,
                  const uint32_t* __restrict__ B,
                  const float* __restrict__ bias,
                  float* __restrict__ C32,
                  uint32_t* __restrict__ Ch, uint32_t* __restrict__ Cl,
                  int M, int N, int K, int split_out)
{
    extern __shared__ char smem[];
    const uint32_t sb = (smem_u32(smem) + 127) & ~127u;

    const int tid  = threadIdx.x;
    const int lane = tid & 31;
    const int wid  = tid >> 5;
    const int wm   = wid & 1;
    const int wn   = wid >> 1;
    const int m0   = blockIdx.y * 128;
    const int n0   = blockIdx.x * 128;
    const int Kw   = K >> 1;          // u32 words per row

    float acc[4][4][4];
    #pragma unroll
    for (int i = 0; i < 4; i++)
        #pragma unroll
        for (int j = 0; j < 4; j++)
            #pragma unroll
            for (int q = 0; q < 4; q++) acc[i][j][q] = 0.f;

    // Each thread copies one 32B half-row per tile per stage.
    const int row  = tid >> 1;
    const int half = tid & 1;
    const uint32_t soff = (uint32_t)(row * RS + half * 32);

    const uint32_t* gAh = Ah + (size_t)(m0 + row) * Kw + half * 8;
    const uint32_t* gAl = Al + (size_t)(m0 + row) * Kw + half * 8;
    const uint32_t* gB  = B  + (size_t)(n0 + row) * Kw + half * 8;

    const uint32_t aLane = (uint32_t)((wm * 64 + (lane & 15)) * RS
                                      + (lane >> 4) * 16);
    const uint32_t bLane = (uint32_t)((wn * 32 + ((lane >> 4) & 1) * 8
                                       + (lane & 7)) * RS
                                      + ((lane >> 3) & 1) * 16);

    const int NIT = K / 32;

    // issue stage 0
    {
        const uint32_t d = sb + soff;
        cp16(d,              gAh); cp16(d + 16,              gAh + 4);
        cp16(d + TILE_B,     gAl); cp16(d + TILE_B + 16,     gAl + 4);
        cp16(d + 2 * TILE_B, gB ); cp16(d + 2 * TILE_B + 16, gB  + 4);
        cp_commit();
    }

    for (int it = 0; it < NIT; ++it) {
        cp_wait0();
        __syncthreads();

        if (it + 1 < NIT) {
            const uint32_t d  = sb + (uint32_t)(((it + 1) & 1) * STAGE_B) + soff;
            const int      ko = (it + 1) * 16;   // u32 offset along K
            cp16(d,              gAh + ko); cp16(d + 16,              gAh + ko + 4);
            cp16(d + TILE_B,     gAl + ko); cp16(d + TILE_B + 16,     gAl + ko + 4);
            cp16(d + 2 * TILE_B, gB  + ko); cp16(d + 2 * TILE_B + 16, gB  + ko + 4);
            cp_commit();
        }

        const uint32_t cur   = sb + (uint32_t)((it & 1) * STAGE_B);
        const uint32_t aAddr = cur + aLane;
        const uint32_t bAddr = cur + 2 * TILE_B + bLane;

        #pragma unroll
        for (int ks = 0; ks < 2; ks++) {
            const uint32_t ko = (uint32_t)(ks * 32);

            uint32_t afh[4][4], afl[4][4], bf[4][2];
            #pragma unroll
            for (int mi = 0; mi < 4; mi++)
                ldm_x4(afh[mi], aAddr + (uint32_t)(mi * 16 * RS) + ko);
            #pragma unroll
            for (int mi = 0; mi < 4; mi++)
                ldm_x4(afl[mi], aAddr + (uint32_t)(TILE_B + mi * 16 * RS) + ko);
            #pragma unroll
            for (int j2 = 0; j2 < 2; j2++) {
                uint32_t t[4];
                ldm_x4(t, bAddr + (uint32_t)(j2 * 16 * RS) + ko);
                bf[2*j2][0] = t[0]; bf[2*j2][1] = t[1];
                bf[2*j2+1][0] = t[2]; bf[2*j2+1][1] = t[3];
            }

            // term 1: Ah x B
            #pragma unroll
            for (int mi = 0; mi < 4; mi++)
                #pragma unroll
                for (int nj = 0; nj < 4; nj++)
                    mma_f16(acc[mi][nj], afh[mi], bf[nj][0], bf[nj][1]);
            // term 2: Al x B
            #pragma unroll
            for (int mi = 0; mi < 4; mi++)
                #pragma unroll
                for (int nj = 0; nj < 4; nj++)
                    mma_f16(acc[mi][nj], afl[mi], bf[nj][0], bf[nj][1]);
        }
    }

    const int g = lane >> 2;
    const int s = lane & 3;
    if (split_out) {
        const int Nw = N >> 1;
        #pragma unroll
        for (int mi = 0; mi < 4; mi++) {
            const int mrow = m0 + wm * 64 + mi * 16 + g;
            #pragma unroll
            for (int nj = 0; nj < 4; nj++) {
                const int ncol = n0 + wn * 32 + nj * 8 + s * 2;
                float2 bv = *(const float2*)(bias + ncol);
                float v0 = acc[mi][nj][0] + bv.x;
                float v1 = acc[mi][nj][1] + bv.y;
                float v2 = acc[mi][nj][2] + bv.x;
                float v3 = acc[mi][nj][3] + bv.y;
                uint32_t hw0 = packh(v0, v1);
                uint32_t hw1 = packh(v2, v3);
                const size_t i0 = (size_t)mrow * Nw + (ncol >> 1);
                const size_t i1 = (size_t)(mrow + 8) * Nw + (ncol >> 1);
                Ch[i0] = hw0;  Cl[i0] = lo_packh(hw0, v0, v1);
                Ch[i1] = hw1;  Cl[i1] = lo_packh(hw1, v2, v3);
            }
        }
    } else {
        #pragma unroll
        for (int mi = 0; mi < 4; mi++) {
            const int mrow = m0 + wm * 64 + mi * 16 + g;
            #pragma unroll
            for (int nj = 0; nj < 4; nj++) {
                const int ncol = n0 + wn * 32 + nj * 8 + s * 2;
                float2 bv = *(const float2*)(bias + ncol);
                float2 o0, o1;
                o0.x = acc[mi][nj][0] + bv.x;  o0.y = acc[mi][nj][1] + bv.y;
                o1.x = acc[mi][nj][2] + bv.x;  o1.y = acc[mi][nj][3] + bv.y;
                *(float2*)(C32 + (size_t)mrow * N + ncol)       = o0;
                *(float2*)(C32 + (size_t)(mrow + 8) * N + ncol) = o1;
            }
        }
    }
}

// ===========================================================================
// Tensor-core flash attention (causal), fp16 asymmetric:
//   S = (Qh+Ql) @ K^T  (K single fp16);  O += (Ph+Pl) @ V  (V single fp16).
// 64-row Q tile, 128 threads / 4 warps (round-11 proven structure).
// smem: QH, QL + 2 stages x (K, V) = 6 x 9216 -> 4 CTA/SM.
// ===========================================================================
#define AT_RS   144
#define AT_T64  (64 * AT_RS)                 // 9216
#define AT_QH   0
#define AT_QL   (1 * AT_T64)
#define AT_KV0  (2 * AT_T64)                 // stage s at AT_KV0 + s*2*AT_T64
#define AT_SMEM (6 * AT_T64 + 128)           // 55424

__global__ void __launch_bounds__(128)
flash_attn_mma(const uint32_t* __restrict__ qh, const uint32_t* __restrict__ ql,
               uint32_t* __restrict__ ah, uint32_t* __restrict__ al)
{
    extern __shared__ char smem[];
    const uint32_t sb = (smem_u32(smem) + 127) & ~127u;

    const int iq   = (int)gridDim.x - 1 - (int)blockIdx.x;   // heavy first
    const int h    = blockIdx.y;
    const int b    = blockIdx.z;
    const int tid  = threadIdx.x;
    const int lane = tid & 31;
    const int w    = tid >> 5;

    const uint32_t* baseh = qh + (size_t)b * TT * QW + h * 96;  // h*192 fp16
    const uint32_t* basel = ql + (size_t)b * TT * QW + h * 96;

    // Q: 64 rows x 8 chunks(16B) = 512 chunks per tile (hi & lo)
    {
        #pragma unroll
        for (int itx = 0; itx < 4; itx++) {
            const int f = tid + itx * 128;
            const int r = f >> 3, c = f & 7;
            const size_t go = (size_t)(iq * 64 + r) * QW + c * 4;
            const uint32_t off = (uint32_t)(r * AT_RS + c * 16);
            cp16(sb + AT_QH + off, baseh + go);
            cp16(sb + AT_QL + off, basel + go);
        }
    }
    auto issueKV = [&](int j, int stg) {
        const uint32_t st = sb + AT_KV0 + (uint32_t)(stg * 2 * AT_T64);
        #pragma unroll
        for (int itx = 0; itx < 4; itx++) {
            const int f = tid + itx * 128;
            const int r = f >> 3, c = f & 7;
            const size_t go = (size_t)(j * 64 + r) * QW + 32 + c * 4;  // K words
            const uint32_t off = (uint32_t)(r * AT_RS + c * 16);
            cp16(st + off,          baseh + go);        // K (hi only)
            cp16(st + AT_T64 + off, baseh + go + 32);   // V (hi only)
        }
    };

    issueKV(0, 0);
    cp_commit();

    const int g = lane >> 2;
    const int s = lane & 3;

    const uint32_t aQ = sb + AT_QH +
        (uint32_t)((w * 16 + (lane & 15)) * AT_RS + (lane >> 4) * 16);
    const uint32_t kLane =
        (uint32_t)((((lane >> 4) & 1) * 8 + (lane & 7)) * AT_RS
                   + ((lane >> 3) & 1) * 16);
    const uint32_t vLane =
        (uint32_t)((((lane >> 3) & 1) * 8 + (lane & 7)) * AT_RS
                   + ((lane >> 4) & 1) * 16);

    float m0v = -1e30f, m1v = -1e30f, l0v = 0.f, l1v = 0.f;
    float o[8][4];
    #pragma unroll
    for (int nt = 0; nt < 8; nt++)
        #pragma unroll
        for (int q = 0; q < 4; q++) o[nt][q] = 0.f;

    const int qrow0 = iq * 64 + w * 16 + g;

    for (int j = 0; j <= iq; j++) {
        const int cur = j & 1;
        cp_wait0();
        __syncthreads();
        if (j < iq) {
            issueKV(j + 1, cur ^ 1);
            cp_commit();
        }

        const uint32_t st = sb + AT_KV0 + (uint32_t)(cur * 2 * AT_T64);
        const uint32_t bK = st + kLane;
        const uint32_t bV = st + AT_T64 + vLane;

        // ---- S = (Qh+Ql) @ K^T (fp32 accum) ----
        float sacc[8][4];
        #pragma unroll
        for (int nt = 0; nt < 8; nt++)
            #pragma unroll
            for (int q = 0; q < 4; q++) sacc[nt][q] = 0.f;

        #pragma unroll
        for (int ks = 0; ks < 4; ks++) {
            const uint32_t ko = (uint32_t)(ks * 32);
            uint32_t qhf[4], qlf[4];
            ldm_x4(qhf, aQ + ko);
            ldm_x4(qlf, aQ + (uint32_t)AT_T64 + ko);
            #pragma unroll
            for (int nb = 0; nb < 4; nb++) {
                uint32_t t[4];
                ldm_x4(t, bK + (uint32_t)(nb * 16 * AT_RS) + ko);
                mma_f16(sacc[2*nb],   qhf, t[0], t[1]);
                mma_f16(sacc[2*nb+1], qhf, t[2], t[3]);
                mma_f16(sacc[2*nb],   qlf, t[0], t[1]);
                mma_f16(sacc[2*nb+1], qlf, t[2], t[3]);
            }
        }

        // scale 1/sqrt(hd) = 0.125
        #pragma unroll
        for (int nt = 0; nt < 8; nt++) {
            sacc[nt][0] *= 0.125f; sacc[nt][1] *= 0.125f;
            sacc[nt][2] *= 0.125f; sacc[nt][3] *= 0.125f;
        }

        // ---- causal mask (diag block only) ----
        if (j == iq) {
            #pragma unroll
            for (int nt = 0; nt < 8; nt++) {
                const int col = j * 64 + nt * 8 + s * 2;
                if (col     > qrow0)     sacc[nt][0] = -1e30f;
                if (col + 1 > qrow0)     sacc[nt][1] = -1e30f;
                if (col     > qrow0 + 8) sacc[nt][2] = -1e30f;
                if (col + 1 > qrow0 + 8) sacc[nt][3] = -1e30f;
            }
        }

        // ---- online softmax on fragments ----
        float mx0 = -1e30f, mx1 = -1e30f;
        #pragma unroll
        for (int nt = 0; nt < 8; nt++) {
            mx0 = fmaxf(mx0, fmaxf(sacc[nt][0], sacc[nt][1]));
            mx1 = fmaxf(mx1, fmaxf(sacc[nt][2], sacc[nt][3]));
        }
        mx0 = fmaxf(mx0, __shfl_xor_sync(0xffffffffu, mx0, 1));
        mx0 = fmaxf(mx0, __shfl_xor_sync(0xffffffffu, mx0, 2));
        mx1 = fmaxf(mx1, __shfl_xor_sync(0xffffffffu, mx1, 1));
        mx1 = fmaxf(mx1, __shfl_xor_sync(0xffffffffu, mx1, 2));

        const float mn0 = fmaxf(m0v, mx0);
        const float mn1 = fmaxf(m1v, mx1);
        const float cr0 = __expf(m0v - mn0);
        const float cr1 = __expf(m1v - mn1);

        float rs0 = 0.f, rs1 = 0.f;
        #pragma unroll
        for (int nt = 0; nt < 8; nt++) {
            float p0 = __expf(sacc[nt][0] - mn0);
            float p1 = __expf(sacc[nt][1] - mn0);
            float p2 = __expf(sacc[nt][2] - mn1);
            float p3 = __expf(sacc[nt][3] - mn1);
            sacc[nt][0] = p0; sacc[nt][1] = p1;
            sacc[nt][2] = p2; sacc[nt][3] = p3;
            rs0 += p0 + p1;
            rs1 += p2 + p3;
        }
        rs0 += __shfl_xor_sync(0xffffffffu, rs0, 1);
        rs0 += __shfl_xor_sync(0xffffffffu, rs0, 2);
        rs1 += __shfl_xor_sync(0xffffffffu, rs1, 1);
        rs1 += __shfl_xor_sync(0xffffffffu, rs1, 2);

        l0v = l0v * cr0 + rs0;
        l1v = l1v * cr1 + rs1;
        m0v = mn0;
        m1v = mn1;
        #pragma unroll
        for (int nt = 0; nt < 8; nt++) {
            o[nt][0] *= cr0; o[nt][1] *= cr0;
            o[nt][2] *= cr1; o[nt][3] *= cr1;
        }

        // ---- O += (Ph+Pl) @ V (P hi/lo from registers, V single fp16) ----
        #pragma unroll
        for (int ks = 0; ks < 4; ks++) {
            uint32_t ph[4], pl[4];
            ph[0] = packh(sacc[2*ks][0],   sacc[2*ks][1]);
            ph[1] = packh(sacc[2*ks][2],   sacc[2*ks][3]);
            ph[2] = packh(sacc[2*ks+1][0], sacc[2*ks+1][1]);
            ph[3] = packh(sacc[2*ks+1][2], sacc[2*ks+1][3]);
            pl[0] = lo_packh(ph[0], sacc[2*ks][0],   sacc[2*ks][1]);
            pl[1] = lo_packh(ph[1], sacc[2*ks][2],   sacc[2*ks][3]);
            pl[2] = lo_packh(ph[2], sacc[2*ks+1][0], sacc[2*ks+1][1]);
            pl[3] = lo_packh(ph[3], sacc[2*ks+1][2], sacc[2*ks+1][3]);

            const uint32_t krow = (uint32_t)(ks * 16 * AT_RS);
            #pragma unroll
            for (int nb = 0; nb < 4; nb++) {
                uint32_t t[4];
                ldm_x4_t(t, bV + krow + (uint32_t)(nb * 32));
                mma_f16(o[2*nb],   ph, t[0], t[1]);
                mma_f16(o[2*nb+1], ph, t[2], t[3]);
                mma_f16(o[2*nb],   pl, t[0], t[1]);
                mma_f16(o[2*nb+1], pl, t[2], t[3]);
            }
        }
    }

    // ---- epilogue: normalize, write attn as hi/lo fp16 [B*T, D/2 u32] ----
    const float inv0 = 1.f / l0v;
    const float inv1 = 1.f / l1v;
    const size_t r0 = (size_t)b * TT + iq * 64 + w * 16 + g;
    #pragma unroll
    for (int nt = 0; nt < 8; nt++) {
        const int colw = h * 32 + nt * 4 + s;   // u32 column
        float v0 = o[nt][0] * inv0, v1 = o[nt][1] * inv0;
        float v2 = o[nt][2] * inv1, v3 = o[nt][3] * inv1;
        uint32_t h0 = packh(v0, v1);
        uint32_t h1 = packh(v2, v3);
        ah[r0 * DW + colw]       = h0;
        al[r0 * DW + colw]       = lo_packh(h0, v0, v1);
        ah[(r0 + 8) * DW + colw] = h1;
        al[(r0 + 8) * DW + colw] = lo_packh(h1, v2, v3);
    }
}

// ===========================================================================
// Launch: splits -> qkv GEMM (split-out) -> flash (split-out) -> out GEMM.
// ===========================================================================
extern "C" void kernel_launch(void* const* d_in, const int* in_sizes, int n_in,
                              void* d_out, int out_size)
{
    const float* x    = (const float*)d_in[0];
    const float* Wqkv = (const float*)d_in[1];
    const float* bqkv = (const float*)d_in[2];
    const float* Wout = (const float*)d_in[3];
    const float* bout = (const float*)d_in[4];
    float*       out  = (float*)d_out;

    uint32_t *xh, *xl, *wq, *wo, *qhp, *qlp, *ahp, *alp;
    cudaGetSymbolAddress((void**)&xh,  g_xh);
    cudaGetSymbolAddress((void**)&xl,  g_xl);
    cudaGetSymbolAddress((void**)&wq,  g_wq);
    cudaGetSymbolAddress((void**)&wo,  g_wo);
    cudaGetSymbolAddress((void**)&qhp, g_qh);
    cudaGetSymbolAddress((void**)&qlp, g_ql);
    cudaGetSymbolAddress((void**)&ahp, g_ah);
    cudaGetSymbolAddress((void**)&alp, g_al);

    cudaFuncSetAttribute(fp16x2_gemm_async,
                         cudaFuncAttributeMaxDynamicSharedMemorySize, GK_SMEM);
    cudaFuncSetAttribute(flash_attn_mma,
                         cudaFuncAttributeMaxDynamicSharedMemorySize, AT_SMEM);

    // 0) pre-passes: x -> hi/lo fp16; weights -> single fp16
    {
        int n4;
        n4 = MROWS * DD / 4;
        split_f32h<<<(n4 + 255) / 256, 256>>>((const float4*)x,
                                              (uint2*)xh, (uint2*)xl, n4);
        n4 = NQKV * DD / 4;
        conv_f32h<<<(n4 + 255) / 256, 256>>>((const float4*)Wqkv, (uint2*)wq, n4);
        n4 = DD * DD / 4;
        conv_f32h<<<(n4 + 255) / 256, 256>>>((const float4*)Wout, (uint2*)wo, n4);
    }
    // 1) qkv = x @ Wqkv^T + bqkv -> hi/lo fp16
    {
        dim3 grid(NQKV / 128, MROWS / 128);   // (24, 32)
        fp16x2_gemm_async<<<grid, 256, GK_SMEM>>>(xh, xl, wq, bqkv,
                                                  nullptr, qhp, qlp,
                                                  MROWS, NQKV, DD, 1);
    }
    // 2) attention -> hi/lo fp16 (64-row Q tiles)
    {
        dim3 grid(TT / 64, HH, BB);           // (32, 16, 2)
        flash_attn_mma<<<grid, 128, AT_SMEM>>>(qhp, qlp, ahp, alp);
    }
    // 3) out = attn @ Wout^T + bout (fp32)
    {
        dim3 grid(DD / 128, MROWS / 128);     // (8, 32)
        fp16x2_gemm_async<<<grid, 256, GK_SMEM>>>(ahp, alp, wo, bout,
                                                  out, nullptr, nullptr,
                                                  MROWS, DD, DD, 0);
    }
}

// round 14
// speedup vs baseline: 1.8635x; 1.2765x over previous
#include <cuda_runtime.h>
#include <cuda_fp16.h>
#include <cstdint>

// Problem constants (fixed by the dataset instance)
#define BB    2
#define TT    2048
#define DD    1024
#define HH    16
#define HDIM  64
#define NQKV  (3*DD)          // 3072
#define MROWS (BB*TT)         // 4096
#define DW    (DD/2)          // u32 words per D-wide row (512)
#define QW    (NQKV/2)        // u32 words per qkv row (1536)

// Scratch (allocation-free rule: __device__ globals). All fp16x2-packed (u32).
__device__ uint32_t g_x  [(size_t)MROWS * DW];               // x single fp16
__device__ uint32_t g_wq [(size_t)NQKV  * DW];               // Wqkv single fp16
__device__ uint32_t g_wo [(size_t)DD    * DW];               // Wout  single fp16
__device__ uint32_t g_qh [(size_t)MROWS * QW], g_ql [(size_t)MROWS * QW];
__device__ uint32_t g_ah [(size_t)MROWS * DW];               // attn single fp16

// ===========================================================================
// Baseline-PTX helpers (no sm_103a-gated instructions).
// ===========================================================================
__device__ __forceinline__ uint32_t smem_u32(const void* p) {
    uint32_t a;
    asm("{ .reg .u64 t; cvta.to.shared.u64 t, %1; cvt.u32.u64 %0, t; }"
        : "=r"(a) : "l"(p));
    return a;
}

__device__ __forceinline__ void ldm_x4(uint32_t r[4], uint32_t addr) {
    asm volatile("ldmatrix.sync.aligned.m8n8.x4.shared.b16 {%0,%1,%2,%3}, [%4];"
                 : "=r"(r[0]), "=r"(r[1]), "=r"(r[2]), "=r"(r[3]) : "r"(addr));
}

__device__ __forceinline__ void ldm_x4_t(uint32_t r[4], uint32_t addr) {
    asm volatile("ldmatrix.sync.aligned.m8n8.x4.trans.shared.b16 {%0,%1,%2,%3}, [%4];"
                 : "=r"(r[0]), "=r"(r[1]), "=r"(r[2]), "=r"(r[3]) : "r"(addr));
}

__device__ __forceinline__ void mma_f16(float c[4], const uint32_t a[4],
                                        uint32_t b0, uint32_t b1) {
    asm volatile(
        "mma.sync.aligned.m16n8k16.row.col.f32.f16.f16.f32 "
        "{%0,%1,%2,%3}, {%4,%5,%6,%7}, {%8,%9}, {%0,%1,%2,%3};"
        : "+f"(c[0]), "+f"(c[1]), "+f"(c[2]), "+f"(c[3])
        : "r"(a[0]), "r"(a[1]), "r"(a[2]), "r"(a[3]), "r"(b0), "r"(b1));
}

// pack two floats into f16x2: first arg -> LOW 16 bits (even-k element)
__device__ __forceinline__ uint32_t packh(float lo, float hi) {
    uint32_t r;
    asm("cvt.rn.f16x2.f32 %0, %1, %2;" : "=r"(r) : "f"(hi), "f"(lo));
    return r;
}

// residual (lo) pair for a given hi-pack
__device__ __forceinline__ uint32_t lo_packh(uint32_t hpk, float f0, float f1) {
    float h0 = __half2float(__ushort_as_half((unsigned short)(hpk & 0xffffu)));
    float h1 = __half2float(__ushort_as_half((unsigned short)(hpk >> 16)));
    return packh(f0 - h0, f1 - h1);
}

__device__ __forceinline__ void cp16(uint32_t dst, const uint32_t* src) {
    asm volatile("cp.async.cg.shared.global [%0], [%1], 16;"
                 :: "r"(dst), "l"(src) : "memory");
}
__device__ __forceinline__ void cp_commit() {
    asm volatile("cp.async.commit_group;" ::: "memory");
}
__device__ __forceinline__ void cp_wait0() {
    asm volatile("cp.async.wait_group 0;" ::: "memory");
}

// ===========================================================================
// Pre-pass: fp32 -> single fp16 (packed u32 pairs).
// ===========================================================================
__global__ void conv_f32h(const float4* __restrict__ src, uint2* __restrict__ h,
                          int n4)
{
    int i = blockIdx.x * 256 + threadIdx.x;
    if (i < n4) {
        float4 v = src[i];
        h[i] = make_uint2(packh(v.x, v.y), packh(v.z, v.w));
    }
}

// ===========================================================================
// fp16 1-term GEMM, cp.async 2-stage pipeline.
// C[M,N] = A[M,K] @ B[N,K]^T + bias[N];  A, B single fp16 (u32-packed).
// CTA 128x128, 8 warps (warp tile 64x32), K-step 32, fp32 accumulate.
// split_out=1: write C as hi/lo fp16. split_out=0: fp32 C32.
// ===========================================================================
#define RS 80
#define TILE_B (128 * RS)          // 10240
#define STAGE_B (2 * TILE_B)       // A, B
#define GK_SMEM (2 * STAGE_B + 128)

__global__ void __launch_bounds__(256, 2)
fp16_gemm_async(const uint32_t* __restrict__ A, const uint32_t* __restrict__ B,
                const float* __restrict__ bias,
                float* __restrict__ C32,
                uint32_t* __restrict__ Ch, uint32_t* __restrict__ Cl,
                int M, int N, int K, int split_out)
{
    extern __shared__ char smem[];
    const uint32_t sb = (smem_u32(smem) + 127) & ~127u;

    const int tid  = threadIdx.x;
    const int lane = tid & 31;
    const int wid  = tid >> 5;
    const int wm   = wid & 1;
    const int wn   = wid >> 1;
    const int m0   = blockIdx.y * 128;
    const int n0   = blockIdx.x * 128;
    const int Kw   = K >> 1;          // u32 words per row

    float acc[4][4][4];
    #pragma unroll
    for (int i = 0; i < 4; i++)
        #pragma unroll
        for (int j = 0; j < 4; j++)
            #pragma unroll
            for (int q = 0; q < 4; q++) acc[i][j][q] = 0.f;

    // Each thread copies one 32B half-row per tile per stage.
    const int row  = tid >> 1;
    const int half = tid & 1;
    const uint32_t soff = (uint32_t)(row * RS + half * 32);

    const uint32_t* gA = A + (size_t)(m0 + row) * Kw + half * 8;
    const uint32_t* gB = B + (size_t)(n0 + row) * Kw + half * 8;

    const uint32_t aLane = (uint32_t)((wm * 64 + (lane & 15)) * RS
                                      + (lane >> 4) * 16);
    const uint32_t bLane = (uint32_t)((wn * 32 + ((lane >> 4) & 1) * 8
                                       + (lane & 7)) * RS
                                      + ((lane >> 3) & 1) * 16);

    const int NIT = K / 32;

    // issue stage 0
    {
        const uint32_t d = sb + soff;
        cp16(d,          gA); cp16(d + 16,          gA + 4);
        cp16(d + TILE_B, gB); cp16(d + TILE_B + 16, gB + 4);
        cp_commit();
    }

    for (int it = 0; it < NIT; ++it) {
        cp_wait0();
        __syncthreads();

        if (it + 1 < NIT) {
            const uint32_t d  = sb + (uint32_t)(((it + 1) & 1) * STAGE_B) + soff;
            const int      ko = (it + 1) * 16;   // u32 offset along K
            cp16(d,          gA + ko); cp16(d + 16,          gA + ko + 4);
            cp16(d + TILE_B, gB + ko); cp16(d + TILE_B + 16, gB + ko + 4);
            cp_commit();
        }

        const uint32_t cur   = sb + (uint32_t)((it & 1) * STAGE_B);
        const uint32_t aAddr = cur + aLane;
        const uint32_t bAddr = cur + TILE_B + bLane;

        #pragma unroll
        for (int ks = 0; ks < 2; ks++) {
            const uint32_t ko = (uint32_t)(ks * 32);

            uint32_t af[4][4], bf[4][2];
            #pragma unroll
            for (int mi = 0; mi < 4; mi++)
                ldm_x4(af[mi], aAddr + (uint32_t)(mi * 16 * RS) + ko);
            #pragma unroll
            for (int j2 = 0; j2 < 2; j2++) {
                uint32_t t[4];
                ldm_x4(t, bAddr + (uint32_t)(j2 * 16 * RS) + ko);
                bf[2*j2][0] = t[0]; bf[2*j2][1] = t[1];
                bf[2*j2+1][0] = t[2]; bf[2*j2+1][1] = t[3];
            }

            #pragma unroll
            for (int mi = 0; mi < 4; mi++)
                #pragma unroll
                for (int nj = 0; nj < 4; nj++)
                    mma_f16(acc[mi][nj], af[mi], bf[nj][0], bf[nj][1]);
        }
    }

    const int g = lane >> 2;
    const int s = lane & 3;
    if (split_out) {
        const int Nw = N >> 1;
        #pragma unroll
        for (int mi = 0; mi < 4; mi++) {
            const int mrow = m0 + wm * 64 + mi * 16 + g;
            #pragma unroll
            for (int nj = 0; nj < 4; nj++) {
                const int ncol = n0 + wn * 32 + nj * 8 + s * 2;
                float2 bv = *(const float2*)(bias + ncol);
                float v0 = acc[mi][nj][0] + bv.x;
                float v1 = acc[mi][nj][1] + bv.y;
                float v2 = acc[mi][nj][2] + bv.x;
                float v3 = acc[mi][nj][3] + bv.y;
                uint32_t hw0 = packh(v0, v1);
                uint32_t hw1 = packh(v2, v3);
                const size_t i0 = (size_t)mrow * Nw + (ncol >> 1);
                const size_t i1 = (size_t)(mrow + 8) * Nw + (ncol >> 1);
                Ch[i0] = hw0;  Cl[i0] = lo_packh(hw0, v0, v1);
                Ch[i1] = hw1;  Cl[i1] = lo_packh(hw1, v2, v3);
            }
        }
    } else {
        #pragma unroll
        for (int mi = 0; mi < 4; mi++) {
            const int mrow = m0 + wm * 64 + mi * 16 + g;
            #pragma unroll
            for (int nj = 0; nj < 4; nj++) {
                const int ncol = n0 + wn * 32 + nj * 8 + s * 2;
                float2 bv = *(const float2*)(bias + ncol);
                float2 o0, o1;
                o0.x = acc[mi][nj][0] + bv.x;  o0.y = acc[mi][nj][1] + bv.y;
                o1.x = acc[mi][nj][2] + bv.x;  o1.y = acc[mi][nj][3] + bv.y;
                *(float2*)(C32 + (size_t)mrow * N + ncol)       = o0;
                *(float2*)(C32 + (size_t)(mrow + 8) * N + ncol) = o1;
            }
        }
    }
}

// ===========================================================================
// Tensor-core flash attention (causal), fp16 asymmetric (round-13 proven):
//   S = (Qh+Ql) @ K^T  (K single fp16);  O += (Ph+Pl) @ V  (V single fp16).
// 64-row Q tile, 128 threads / 4 warps. Epilogue writes attn SINGLE fp16.
// smem: QH, QL + 2 stages x (K, V) = 6 x 9216.
// ===========================================================================
#define AT_RS   144
#define AT_T64  (64 * AT_RS)                 // 9216
#define AT_QH   0
#define AT_QL   (1 * AT_T64)
#define AT_KV0  (2 * AT_T64)                 // stage s at AT_KV0 + s*2*AT_T64
#define AT_SMEM (6 * AT_T64 + 128)           // 55424

__global__ void __launch_bounds__(128)
flash_attn_mma(const uint32_t* __restrict__ qh, const uint32_t* __restrict__ ql,
               uint32_t* __restrict__ ah)
{
    extern __shared__ char smem[];
    const uint32_t sb = (smem_u32(smem) + 127) & ~127u;

    const int iq   = (int)gridDim.x - 1 - (int)blockIdx.x;   // heavy first
    const int h    = blockIdx.y;
    const int b    = blockIdx.z;
    const int tid  = threadIdx.x;
    const int lane = tid & 31;
    const int w    = tid >> 5;

    const uint32_t* baseh = qh + (size_t)b * TT * QW + h * 96;  // h*192 fp16
    const uint32_t* basel = ql + (size_t)b * TT * QW + h * 96;

    // Q: 64 rows x 8 chunks(16B) = 512 chunks per tile (hi & lo)
    {
        #pragma unroll
        for (int itx = 0; itx < 4; itx++) {
            const int f = tid + itx * 128;
            const int r = f >> 3, c = f & 7;
            const size_t go = (size_t)(iq * 64 + r) * QW + c * 4;
            const uint32_t off = (uint32_t)(r * AT_RS + c * 16);
            cp16(sb + AT_QH + off, baseh + go);
            cp16(sb + AT_QL + off, basel + go);
        }
    }
    auto issueKV = [&](int j, int stg) {
        const uint32_t st = sb + AT_KV0 + (uint32_t)(stg * 2 * AT_T64);
        #pragma unroll
        for (int itx = 0; itx < 4; itx++) {
            const int f = tid + itx * 128;
            const int r = f >> 3, c = f & 7;
            const size_t go = (size_t)(j * 64 + r) * QW + 32 + c * 4;  // K words
            const uint32_t off = (uint32_t)(r * AT_RS + c * 16);
            cp16(st + off,          baseh + go);        // K (hi only)
            cp16(st + AT_T64 + off, baseh + go + 32);   // V (hi only)
        }
    };

    issueKV(0, 0);
    cp_commit();

    const int g = lane >> 2;
    const int s = lane & 3;

    const uint32_t aQ = sb + AT_QH +
        (uint32_t)((w * 16 + (lane & 15)) * AT_RS + (lane >> 4) * 16);
    const uint32_t kLane =
        (uint32_t)((((lane >> 4) & 1) * 8 + (lane & 7)) * AT_RS
                   + ((lane >> 3) & 1) * 16);
    const uint32_t vLane =
        (uint32_t)((((lane >> 3) & 1) * 8 + (lane & 7)) * AT_RS
                   + ((lane >> 4) & 1) * 16);

    float m0v = -1e30f, m1v = -1e30f, l0v = 0.f, l1v = 0.f;
    float o[8][4];
    #pragma unroll
    for (int nt = 0; nt < 8; nt++)
        #pragma unroll
        for (int q = 0; q < 4; q++) o[nt][q] = 0.f;

    const int qrow0 = iq * 64 + w * 16 + g;

    for (int j = 0; j <= iq; j++) {
        const int cur = j & 1;
        cp_wait0();
        __syncthreads();
        if (j < iq) {
            issueKV(j + 1, cur ^ 1);
            cp_commit();
        }

        const uint32_t st = sb + AT_KV0 + (uint32_t)(cur * 2 * AT_T64);
        const uint32_t bK = st + kLane;
        const uint32_t bV = st + AT_T64 + vLane;

        // ---- S = (Qh+Ql) @ K^T (fp32 accum) ----
        float sacc[8][4];
        #pragma unroll
        for (int nt = 0; nt < 8; nt++)
            #pragma unroll
            for (int q = 0; q < 4; q++) sacc[nt][q] = 0.f;

        #pragma unroll
        for (int ks = 0; ks < 4; ks++) {
            const uint32_t ko = (uint32_t)(ks * 32);
            uint32_t qhf[4], qlf[4];
            ldm_x4(qhf, aQ + ko);
            ldm_x4(qlf, aQ + (uint32_t)AT_T64 + ko);
            #pragma unroll
            for (int nb = 0; nb < 4; nb++) {
                uint32_t t[4];
                ldm_x4(t, bK + (uint32_t)(nb * 16 * AT_RS) + ko);
                mma_f16(sacc[2*nb],   qhf, t[0], t[1]);
                mma_f16(sacc[2*nb+1], qhf, t[2], t[3]);
                mma_f16(sacc[2*nb],   qlf, t[0], t[1]);
                mma_f16(sacc[2*nb+1], qlf, t[2], t[3]);
            }
        }

        // scale 1/sqrt(hd) = 0.125
        #pragma unroll
        for (int nt = 0; nt < 8; nt++) {
            sacc[nt][0] *= 0.125f; sacc[nt][1] *= 0.125f;
            sacc[nt][2] *= 0.125f; sacc[nt][3] *= 0.125f;
        }

        // ---- causal mask (diag block only) ----
        if (j == iq) {
            #pragma unroll
            for (int nt = 0; nt < 8; nt++) {
                const int col = j * 64 + nt * 8 + s * 2;
                if (col     > qrow0)     sacc[nt][0] = -1e30f;
                if (col + 1 > qrow0)     sacc[nt][1] = -1e30f;
                if (col     > qrow0 + 8) sacc[nt][2] = -1e30f;
                if (col + 1 > qrow0 + 8) sacc[nt][3] = -1e30f;
            }
        }

        // ---- online softmax on fragments ----
        float mx0 = -1e30f, mx1 = -1e30f;
        #pragma unroll
        for (int nt = 0; nt < 8; nt++) {
            mx0 = fmaxf(mx0, fmaxf(sacc[nt][0], sacc[nt][1]));
            mx1 = fmaxf(mx1, fmaxf(sacc[nt][2], sacc[nt][3]));
        }
        mx0 = fmaxf(mx0, __shfl_xor_sync(0xffffffffu, mx0, 1));
        mx0 = fmaxf(mx0, __shfl_xor_sync(0xffffffffu, mx0, 2));
        mx1 = fmaxf(mx1, __shfl_xor_sync(0xffffffffu, mx1, 1));
        mx1 = fmaxf(mx1, __shfl_xor_sync(0xffffffffu, mx1, 2));

        const float mn0 = fmaxf(m0v, mx0);
        const float mn1 = fmaxf(m1v, mx1);
        const float cr0 = __expf(m0v - mn0);
        const float cr1 = __expf(m1v - mn1);

        float rs0 = 0.f, rs1 = 0.f;
        #pragma unroll
        for (int nt = 0; nt < 8; nt++) {
            float p0 = __expf(sacc[nt][0] - mn0);
            float p1 = __expf(sacc[nt][1] - mn0);
            float p2 = __expf(sacc[nt][2] - mn1);
            float p3 = __expf(sacc[nt][3] - mn1);
            sacc[nt][0] = p0; sacc[nt][1] = p1;
            sacc[nt][2] = p2; sacc[nt][3] = p3;
            rs0 += p0 + p1;
            rs1 += p2 + p3;
        }
        rs0 += __shfl_xor_sync(0xffffffffu, rs0, 1);
        rs0 += __shfl_xor_sync(0xffffffffu, rs0, 2);
        rs1 += __shfl_xor_sync(0xffffffffu, rs1, 1);
        rs1 += __shfl_xor_sync(0xffffffffu, rs1, 2);

        l0v = l0v * cr0 + rs0;
        l1v = l1v * cr1 + rs1;
        m0v = mn0;
        m1v = mn1;
        #pragma unroll
        for (int nt = 0; nt < 8; nt++) {
            o[nt][0] *= cr0; o[nt][1] *= cr0;
            o[nt][2] *= cr1; o[nt][3] *= cr1;
        }

        // ---- O += (Ph+Pl) @ V (P hi/lo from registers, V single fp16) ----
        #pragma unroll
        for (int ks = 0; ks < 4; ks++) {
            uint32_t ph[4], pl[4];
            ph[0] = packh(sacc[2*ks][0],   sacc[2*ks][1]);
            ph[1] = packh(sacc[2*ks][2],   sacc[2*ks][3]);
            ph[2] = packh(sacc[2*ks+1][0], sacc[2*ks+1][1]);
            ph[3] = packh(sacc[2*ks+1][2], sacc[2*ks+1][3]);
            pl[0] = lo_packh(ph[0], sacc[2*ks][0],   sacc[2*ks][1]);
            pl[1] = lo_packh(ph[1], sacc[2*ks][2],   sacc[2*ks][3]);
            pl[2] = lo_packh(ph[2], sacc[2*ks+1][0], sacc[2*ks+1][1]);
            pl[3] = lo_packh(ph[3], sacc[2*ks+1][2], sacc[2*ks+1][3]);

            const uint32_t krow = (uint32_t)(ks * 16 * AT_RS);
            #pragma unroll
            for (int nb = 0; nb < 4; nb++) {
                uint32_t t[4];
                ldm_x4_t(t, bV + krow + (uint32_t)(nb * 32));
                mma_f16(o[2*nb],   ph, t[0], t[1]);
                mma_f16(o[2*nb+1], ph, t[2], t[3]);
                mma_f16(o[2*nb],   pl, t[0], t[1]);
                mma_f16(o[2*nb+1], pl, t[2], t[3]);
            }
        }
    }

    // ---- epilogue: normalize, write attn as SINGLE fp16 [B*T, D/2 u32] ----
    const float inv0 = 1.f / l0v;
    const float inv1 = 1.f / l1v;
    const size_t r0 = (size_t)b * TT + iq * 64 + w * 16 + g;
    #pragma unroll
    for (int nt = 0; nt < 8; nt++) {
        const int colw = h * 32 + nt * 4 + s;   // u32 column
        ah[r0 * DW + colw]       = packh(o[nt][0] * inv0, o[nt][1] * inv0);
        ah[(r0 + 8) * DW + colw] = packh(o[nt][2] * inv1, o[nt][3] * inv1);
    }
}

// ===========================================================================
// Launch: convs -> qkv GEMM (split-out) -> flash (hi-out) -> out GEMM.
// ===========================================================================
extern "C" void kernel_launch(void* const* d_in, const int* in_sizes, int n_in,
                              void* d_out, int out_size)
{
    const float* x    = (const float*)d_in[0];
    const float* Wqkv = (const float*)d_in[1];
    const float* bqkv = (const float*)d_in[2];
    const float* Wout = (const float*)d_in[3];
    const float* bout = (const float*)d_in[4];
    float*       out  = (float*)d_out;

    uint32_t *xp, *wq, *wo, *qhp, *qlp, *ahp;
    cudaGetSymbolAddress((void**)&xp,  g_x);
    cudaGetSymbolAddress((void**)&wq,  g_wq);
    cudaGetSymbolAddress((void**)&wo,  g_wo);
    cudaGetSymbolAddress((void**)&qhp, g_qh);
    cudaGetSymbolAddress((void**)&qlp, g_ql);
    cudaGetSymbolAddress((void**)&ahp, g_ah);

    cudaFuncSetAttribute(fp16_gemm_async,
                         cudaFuncAttributeMaxDynamicSharedMemorySize, GK_SMEM);
    cudaFuncSetAttribute(flash_attn_mma,
                         cudaFuncAttributeMaxDynamicSharedMemorySize, AT_SMEM);

    // 0) pre-passes: fp32 -> single fp16
    {
        int n4;
        n4 = MROWS * DD / 4;
        conv_f32h<<<(n4 + 255) / 256, 256>>>((const float4*)x, (uint2*)xp, n4);
        n4 = NQKV * DD / 4;
        conv_f32h<<<(n4 + 255) / 256, 256>>>((const float4*)Wqkv, (uint2*)wq, n4);
        n4 = DD * DD / 4;
        conv_f32h<<<(n4 + 255) / 256, 256>>>((const float4*)Wout, (uint2*)wo, n4);
    }
    // 1) qkv = x @ Wqkv^T + bqkv -> hi/lo fp16 (1-term GEMM)
    {
        dim3 grid(NQKV / 128, MROWS / 128);   // (24, 32)
        fp16_gemm_async<<<grid, 256, GK_SMEM>>>(xp, wq, bqkv,
                                                nullptr, qhp, qlp,
                                                MROWS, NQKV, DD, 1);
    }
    // 2) attention -> single fp16 (64-row Q tiles)
    {
        dim3 grid(TT / 64, HH, BB);           // (32, 16, 2)
        flash_attn_mma<<<grid, 128, AT_SMEM>>>(qhp, qlp, ahp);
    }
    // 3) out = attn @ Wout^T + bout (fp32, 1-term GEMM)
    {
        dim3 grid(DD / 128, MROWS / 128);     // (8, 32)
        fp16_gemm_async<<<grid, 256, GK_SMEM>>>(ahp, wo, bout,
                                                out, nullptr, nullptr,
                                                MROWS, DD, DD, 0);
    }
}

// round 15
// speedup vs baseline: 2.5343x; 1.3600x over previous
#include <cuda_runtime.h>
#include <cuda_fp16.h>
#include <cstdint>

// Problem constants (fixed by the dataset instance)
#define BB    2
#define TT    2048
#define DD    1024
#define HH    16
#define HDIM  64
#define NQKV  (3*DD)          // 3072
#define MROWS (BB*TT)         // 4096
#define DW    (DD/2)          // u32 words per D-wide row (512)
#define QW    (NQKV/2)        // u32 words per qkv row (1536)

// Scratch (allocation-free rule: __device__ globals). All fp16x2-packed (u32).
__device__ uint32_t g_x  [(size_t)MROWS * DW];               // x single fp16
__device__ uint32_t g_wq [(size_t)NQKV  * DW];               // Wqkv single fp16
__device__ uint32_t g_wo [(size_t)DD    * DW];               // Wout  single fp16
__device__ uint32_t g_q  [(size_t)MROWS * QW];               // qkv single fp16
__device__ uint32_t g_a  [(size_t)MROWS * DW];               // attn single fp16

// ===========================================================================
// Baseline-PTX helpers (no sm_103a-gated instructions).
// ===========================================================================
__device__ __forceinline__ uint32_t smem_u32(const void* p) {
    uint32_t a;
    asm("{ .reg .u64 t; cvta.to.shared.u64 t, %1; cvt.u32.u64 %0, t; }"
        : "=r"(a) : "l"(p));
    return a;
}

__device__ __forceinline__ void ldm_x4(uint32_t r[4], uint32_t addr) {
    asm volatile("ldmatrix.sync.aligned.m8n8.x4.shared.b16 {%0,%1,%2,%3}, [%4];"
                 : "=r"(r[0]), "=r"(r[1]), "=r"(r[2]), "=r"(r[3]) : "r"(addr));
}

__device__ __forceinline__ void ldm_x4_t(uint32_t r[4], uint32_t addr) {
    asm volatile("ldmatrix.sync.aligned.m8n8.x4.trans.shared.b16 {%0,%1,%2,%3}, [%4];"
                 : "=r"(r[0]), "=r"(r[1]), "=r"(r[2]), "=r"(r[3]) : "r"(addr));
}

__device__ __forceinline__ void mma_f16(float c[4], const uint32_t a[4],
                                        uint32_t b0, uint32_t b1) {
    asm volatile(
        "mma.sync.aligned.m16n8k16.row.col.f32.f16.f16.f32 "
        "{%0,%1,%2,%3}, {%4,%5,%6,%7}, {%8,%9}, {%0,%1,%2,%3};"
        : "+f"(c[0]), "+f"(c[1]), "+f"(c[2]), "+f"(c[3])
        : "r"(a[0]), "r"(a[1]), "r"(a[2]), "r"(a[3]), "r"(b0), "r"(b1));
}

// pack two floats into f16x2: first arg -> LOW 16 bits (even-k element)
__device__ __forceinline__ uint32_t packh(float lo, float hi) {
    uint32_t r;
    asm("cvt.rn.f16x2.f32 %0, %1, %2;" : "=r"(r) : "f"(hi), "f"(lo));
    return r;
}

__device__ __forceinline__ void cp16(uint32_t dst, const uint32_t* src) {
    asm volatile("cp.async.cg.shared.global [%0], [%1], 16;"
                 :: "r"(dst), "l"(src) : "memory");
}
__device__ __forceinline__ void cp_commit() {
    asm volatile("cp.async.commit_group;" ::: "memory");
}
__device__ __forceinline__ void cp_wait0() {
    asm volatile("cp.async.wait_group 0;" ::: "memory");
}

// ===========================================================================
// Pre-pass: fp32 -> single fp16 (packed u32 pairs).
// ===========================================================================
__global__ void conv_f32h(const float4* __restrict__ src, uint2* __restrict__ h,
                          int n4)
{
    int i = blockIdx.x * 256 + threadIdx.x;
    if (i < n4) {
        float4 v = src[i];
        h[i] = make_uint2(packh(v.x, v.y), packh(v.z, v.w));
    }
}

// ===========================================================================
// fp16 GEMM, cp.async 2-stage pipeline, K=64 per stage (fewer syncs).
// C[M,N] = A[M,K] @ B[N,K]^T + bias[N];  A, B single fp16 (u32-packed).
// CTA 128x128, 8 warps (warp tile 64x32), fp32 accumulate.
// smem rows: 128 fp16 = 128B data, RS=144 stride (conflict-free, proven).
// split_out=1: write C single fp16. split_out=0: fp32 C32.
// ===========================================================================
#define RS 144
#define TILE_B (128 * RS)          // 18432
#define STAGE_B (2 * TILE_B)       // A, B = 36864
#define GK_SMEM (2 * STAGE_B + 128)  // 73856 -> 2 CTA/SM

__global__ void __launch_bounds__(256, 2)
fp16_gemm_async(const uint32_t* __restrict__ A, const uint32_t* __restrict__ B,
                const float* __restrict__ bias,
                float* __restrict__ C32,
                uint32_t* __restrict__ Ch,
                int M, int N, int K, int split_out)
{
    extern __shared__ char smem[];
    const uint32_t sb = (smem_u32(smem) + 127) & ~127u;

    const int tid  = threadIdx.x;
    const int lane = tid & 31;
    const int wid  = tid >> 5;
    const int wm   = wid & 1;
    const int wn   = wid >> 1;
    const int m0   = blockIdx.y * 128;
    const int n0   = blockIdx.x * 128;
    const int Kw   = K >> 1;          // u32 words per row

    float acc[4][4][4];
    #pragma unroll
    for (int i = 0; i < 4; i++)
        #pragma unroll
        for (int j = 0; j < 4; j++)
            #pragma unroll
            for (int q = 0; q < 4; q++) acc[i][j][q] = 0.f;

    // Copy geometry: tile = 128 rows x 8 chunks(16B); 1024 chunks; 4/thread.
    const int cr = tid >> 3;          // base row (advances +32 per itx)
    const int cc = tid & 7;           // 16B chunk column

    const uint32_t aLane = (uint32_t)((wm * 64 + (lane & 15)) * RS
                                      + (lane >> 4) * 16);
    const uint32_t bLane = (uint32_t)((wn * 32 + ((lane >> 4) & 1) * 8
                                       + (lane & 7)) * RS
                                      + ((lane >> 3) & 1) * 16);

    const int NIT = K / 64;

    auto issue = [&](int it, int stg) {
        const uint32_t st = sb + (uint32_t)(stg * STAGE_B);
        const int k0w = it * 32;   // u32 words along K (64 fp16)
        #pragma unroll
        for (int itx = 0; itx < 4; itx++) {
            const int r = cr + itx * 32;
            const uint32_t off = (uint32_t)(r * RS + cc * 16);
            cp16(st + off,          A + (size_t)(m0 + r) * Kw + k0w + cc * 4);
            cp16(st + TILE_B + off, B + (size_t)(n0 + r) * Kw + k0w + cc * 4);
        }
        cp_commit();
    };

    issue(0, 0);

    for (int it = 0; it < NIT; ++it) {
        cp_wait0();
        __syncthreads();

        if (it + 1 < NIT) issue(it + 1, (it + 1) & 1);

        const uint32_t cur   = sb + (uint32_t)((it & 1) * STAGE_B);
        const uint32_t aAddr = cur + aLane;
        const uint32_t bAddr = cur + TILE_B + bLane;

        #pragma unroll
        for (int ks = 0; ks < 4; ks++) {
            const uint32_t ko = (uint32_t)(ks * 32);

            uint32_t af[4][4], bf[4][2];
            #pragma unroll
            for (int mi = 0; mi < 4; mi++)
                ldm_x4(af[mi], aAddr + (uint32_t)(mi * 16 * RS) + ko);
            #pragma unroll
            for (int j2 = 0; j2 < 2; j2++) {
                uint32_t t[4];
                ldm_x4(t, bAddr + (uint32_t)(j2 * 16 * RS) + ko);
                bf[2*j2][0] = t[0]; bf[2*j2][1] = t[1];
                bf[2*j2+1][0] = t[2]; bf[2*j2+1][1] = t[3];
            }

            #pragma unroll
            for (int mi = 0; mi < 4; mi++)
                #pragma unroll
                for (int nj = 0; nj < 4; nj++)
                    mma_f16(acc[mi][nj], af[mi], bf[nj][0], bf[nj][1]);
        }
    }

    const int g = lane >> 2;
    const int s = lane & 3;
    if (split_out) {
        const int Nw = N >> 1;
        #pragma unroll
        for (int mi = 0; mi < 4; mi++) {
            const int mrow = m0 + wm * 64 + mi * 16 + g;
            #pragma unroll
            for (int nj = 0; nj < 4; nj++) {
                const int ncol = n0 + wn * 32 + nj * 8 + s * 2;
                float2 bv = *(const float2*)(bias + ncol);
                Ch[(size_t)mrow * Nw + (ncol >> 1)] =
                    packh(acc[mi][nj][0] + bv.x, acc[mi][nj][1] + bv.y);
                Ch[(size_t)(mrow + 8) * Nw + (ncol >> 1)] =
                    packh(acc[mi][nj][2] + bv.x, acc[mi][nj][3] + bv.y);
            }
        }
    } else {
        #pragma unroll
        for (int mi = 0; mi < 4; mi++) {
            const int mrow = m0 + wm * 64 + mi * 16 + g;
            #pragma unroll
            for (int nj = 0; nj < 4; nj++) {
                const int ncol = n0 + wn * 32 + nj * 8 + s * 2;
                float2 bv = *(const float2*)(bias + ncol);
                float2 o0, o1;
                o0.x = acc[mi][nj][0] + bv.x;  o0.y = acc[mi][nj][1] + bv.y;
                o1.x = acc[mi][nj][2] + bv.x;  o1.y = acc[mi][nj][3] + bv.y;
                *(float2*)(C32 + (size_t)mrow * N + ncol)       = o0;
                *(float2*)(C32 + (size_t)(mrow + 8) * N + ncol) = o1;
            }
        }
    }
}

// ===========================================================================
// Tensor-core flash attention (causal), single fp16 throughout:
//   S = Q @ K^T;  O += P @ V.   fp32 accumulate + fp32 softmax.
// 64-row Q tile, 128 threads / 4 warps, cp.async double-buffered K/V.
// ===========================================================================
#define AT_RS   144
#define AT_T64  (64 * AT_RS)                 // 9216
#define AT_QH   0
#define AT_KV0  (1 * AT_T64)                 // stage s at AT_KV0 + s*2*AT_T64
#define AT_SMEM (5 * AT_T64 + 128)           // 46208

__global__ void __launch_bounds__(128)
flash_attn_mma(const uint32_t* __restrict__ qkv, uint32_t* __restrict__ ao)
{
    extern __shared__ char smem[];
    const uint32_t sb = (smem_u32(smem) + 127) & ~127u;

    const int iq   = (int)gridDim.x - 1 - (int)blockIdx.x;   // heavy first
    const int h    = blockIdx.y;
    const int b    = blockIdx.z;
    const int tid  = threadIdx.x;
    const int lane = tid & 31;
    const int w    = tid >> 5;

    const uint32_t* base = qkv + (size_t)b * TT * QW + h * 96;  // h*192 fp16

    // Q: 64 rows x 8 chunks(16B) = 512 chunks
    {
        #pragma unroll
        for (int itx = 0; itx < 4; itx++) {
            const int f = tid + itx * 128;
            const int r = f >> 3, c = f & 7;
            cp16(sb + AT_QH + (uint32_t)(r * AT_RS + c * 16),
                 base + (size_t)(iq * 64 + r) * QW + c * 4);
        }
    }
    auto issueKV = [&](int j, int stg) {
        const uint32_t st = sb + AT_KV0 + (uint32_t)(stg * 2 * AT_T64);
        #pragma unroll
        for (int itx = 0; itx < 4; itx++) {
            const int f = tid + itx * 128;
            const int r = f >> 3, c = f & 7;
            const size_t go = (size_t)(j * 64 + r) * QW + 32 + c * 4;  // K words
            const uint32_t off = (uint32_t)(r * AT_RS + c * 16);
            cp16(st + off,          base + go);        // K
            cp16(st + AT_T64 + off, base + go + 32);   // V
        }
    };

    issueKV(0, 0);
    cp_commit();

    const int g = lane >> 2;
    const int s = lane & 3;

    const uint32_t aQ = sb + AT_QH +
        (uint32_t)((w * 16 + (lane & 15)) * AT_RS + (lane >> 4) * 16);
    const uint32_t kLane =
        (uint32_t)((((lane >> 4) & 1) * 8 + (lane & 7)) * AT_RS
                   + ((lane >> 3) & 1) * 16);
    const uint32_t vLane =
        (uint32_t)((((lane >> 3) & 1) * 8 + (lane & 7)) * AT_RS
                   + ((lane >> 4) & 1) * 16);

    float m0v = -1e30f, m1v = -1e30f, l0v = 0.f, l1v = 0.f;
    float o[8][4];
    #pragma unroll
    for (int nt = 0; nt < 8; nt++)
        #pragma unroll
        for (int q = 0; q < 4; q++) o[nt][q] = 0.f;

    const int qrow0 = iq * 64 + w * 16 + g;

    for (int j = 0; j <= iq; j++) {
        const int cur = j & 1;
        cp_wait0();
        __syncthreads();
        if (j < iq) {
            issueKV(j + 1, cur ^ 1);
            cp_commit();
        }

        const uint32_t st = sb + AT_KV0 + (uint32_t)(cur * 2 * AT_T64);
        const uint32_t bK = st + kLane;
        const uint32_t bV = st + AT_T64 + vLane;

        // ---- S = Q @ K^T (fp32 accum) ----
        float sacc[8][4];
        #pragma unroll
        for (int nt = 0; nt < 8; nt++)
            #pragma unroll
            for (int q = 0; q < 4; q++) sacc[nt][q] = 0.f;

        #pragma unroll
        for (int ks = 0; ks < 4; ks++) {
            const uint32_t ko = (uint32_t)(ks * 32);
            uint32_t qf[4];
            ldm_x4(qf, aQ + ko);
            #pragma unroll
            for (int nb = 0; nb < 4; nb++) {
                uint32_t t[4];
                ldm_x4(t, bK + (uint32_t)(nb * 16 * AT_RS) + ko);
                mma_f16(sacc[2*nb],   qf, t[0], t[1]);
                mma_f16(sacc[2*nb+1], qf, t[2], t[3]);
            }
        }

        // scale 1/sqrt(hd) = 0.125
        #pragma unroll
        for (int nt = 0; nt < 8; nt++) {
            sacc[nt][0] *= 0.125f; sacc[nt][1] *= 0.125f;
            sacc[nt][2] *= 0.125f; sacc[nt][3] *= 0.125f;
        }

        // ---- causal mask (diag block only) ----
        if (j == iq) {
            #pragma unroll
            for (int nt = 0; nt < 8; nt++) {
                const int col = j * 64 + nt * 8 + s * 2;
                if (col     > qrow0)     sacc[nt][0] = -1e30f;
                if (col + 1 > qrow0)     sacc[nt][1] = -1e30f;
                if (col     > qrow0 + 8) sacc[nt][2] = -1e30f;
                if (col + 1 > qrow0 + 8) sacc[nt][3] = -1e30f;
            }
        }

        // ---- online softmax on fragments ----
        float mx0 = -1e30f, mx1 = -1e30f;
        #pragma unroll
        for (int nt = 0; nt < 8; nt++) {
            mx0 = fmaxf(mx0, fmaxf(sacc[nt][0], sacc[nt][1]));
            mx1 = fmaxf(mx1, fmaxf(sacc[nt][2], sacc[nt][3]));
        }
        mx0 = fmaxf(mx0, __shfl_xor_sync(0xffffffffu, mx0, 1));
        mx0 = fmaxf(mx0, __shfl_xor_sync(0xffffffffu, mx0, 2));
        mx1 = fmaxf(mx1, __shfl_xor_sync(0xffffffffu, mx1, 1));
        mx1 = fmaxf(mx1, __shfl_xor_sync(0xffffffffu, mx1, 2));

        const float mn0 = fmaxf(m0v, mx0);
        const float mn1 = fmaxf(m1v, mx1);
        const float cr0 = __expf(m0v - mn0);
        const float cr1 = __expf(m1v - mn1);

        float rs0 = 0.f, rs1 = 0.f;
        #pragma unroll
        for (int nt = 0; nt < 8; nt++) {
            float p0 = __expf(sacc[nt][0] - mn0);
            float p1 = __expf(sacc[nt][1] - mn0);
            float p2 = __expf(sacc[nt][2] - mn1);
            float p3 = __expf(sacc[nt][3] - mn1);
            sacc[nt][0] = p0; sacc[nt][1] = p1;
            sacc[nt][2] = p2; sacc[nt][3] = p3;
            rs0 += p0 + p1;
            rs1 += p2 + p3;
        }
        rs0 += __shfl_xor_sync(0xffffffffu, rs0, 1);
        rs0 += __shfl_xor_sync(0xffffffffu, rs0, 2);
        rs1 += __shfl_xor_sync(0xffffffffu, rs1, 1);
        rs1 += __shfl_xor_sync(0xffffffffu, rs1, 2);

        l0v = l0v * cr0 + rs0;
        l1v = l1v * cr1 + rs1;
        m0v = mn0;
        m1v = mn1;
        #pragma unroll
        for (int nt = 0; nt < 8; nt++) {
            o[nt][0] *= cr0; o[nt][1] *= cr0;
            o[nt][2] *= cr1; o[nt][3] *= cr1;
        }

        // ---- O += P @ V (P single fp16 from registers, V via ldm.trans) ----
        #pragma unroll
        for (int ks = 0; ks < 4; ks++) {
            uint32_t ph[4];
            ph[0] = packh(sacc[2*ks][0],   sacc[2*ks][1]);
            ph[1] = packh(sacc[2*ks][2],   sacc[2*ks][3]);
            ph[2] = packh(sacc[2*ks+1][0], sacc[2*ks+1][1]);
            ph[3] = packh(sacc[2*ks+1][2], sacc[2*ks+1][3]);

            const uint32_t krow = (uint32_t)(ks * 16 * AT_RS);
            #pragma unroll
            for (int nb = 0; nb < 4; nb++) {
                uint32_t t[4];
                ldm_x4_t(t, bV + krow + (uint32_t)(nb * 32));
                mma_f16(o[2*nb],   ph, t[0], t[1]);
                mma_f16(o[2*nb+1], ph, t[2], t[3]);
            }
        }
    }

    // ---- epilogue: normalize, write attn single fp16 [B*T, D/2 u32] ----
    const float inv0 = 1.f / l0v;
    const float inv1 = 1.f / l1v;
    const size_t r0 = (size_t)b * TT + iq * 64 + w * 16 + g;
    #pragma unroll
    for (int nt = 0; nt < 8; nt++) {
        const int colw = h * 32 + nt * 4 + s;   // u32 column
        ao[r0 * DW + colw]       = packh(o[nt][0] * inv0, o[nt][1] * inv0);
        ao[(r0 + 8) * DW + colw] = packh(o[nt][2] * inv1, o[nt][3] * inv1);
    }
}

// ===========================================================================
// Launch: convs -> qkv GEMM (fp16-out) -> flash (fp16-out) -> out GEMM.
// ===========================================================================
extern "C" void kernel_launch(void* const* d_in, const int* in_sizes, int n_in,
                              void* d_out, int out_size)
{
    const float* x    = (const float*)d_in[0];
    const float* Wqkv = (const float*)d_in[1];
    const float* bqkv = (const float*)d_in[2];
    const float* Wout = (const float*)d_in[3];
    const float* bout = (const float*)d_in[4];
    float*       out  = (float*)d_out;

    uint32_t *xp, *wq, *wo, *qp, *ap;
    cudaGetSymbolAddress((void**)&xp, g_x);
    cudaGetSymbolAddress((void**)&wq, g_wq);
    cudaGetSymbolAddress((void**)&wo, g_wo);
    cudaGetSymbolAddress((void**)&qp, g_q);
    cudaGetSymbolAddress((void**)&ap, g_a);

    cudaFuncSetAttribute(fp16_gemm_async,
                         cudaFuncAttributeMaxDynamicSharedMemorySize, GK_SMEM);
    cudaFuncSetAttribute(flash_attn_mma,
                         cudaFuncAttributeMaxDynamicSharedMemorySize, AT_SMEM);

    // 0) pre-passes: fp32 -> single fp16
    {
        int n4;
        n4 = MROWS * DD / 4;
        conv_f32h<<<(n4 + 255) / 256, 256>>>((const float4*)x, (uint2*)xp, n4);
        n4 = NQKV * DD / 4;
        conv_f32h<<<(n4 + 255) / 256, 256>>>((const float4*)Wqkv, (uint2*)wq, n4);
        n4 = DD * DD / 4;
        conv_f32h<<<(n4 + 255) / 256, 256>>>((const float4*)Wout, (uint2*)wo, n4);
    }
    // 1) qkv = x @ Wqkv^T + bqkv -> single fp16
    {
        dim3 grid(NQKV / 128, MROWS / 128);   // (24, 32)
        fp16_gemm_async<<<grid, 256, GK_SMEM>>>(xp, wq, bqkv,
                                                nullptr, qp,
                                                MROWS, NQKV, DD, 1);
    }
    // 2) attention -> single fp16 (64-row Q tiles)
    {
        dim3 grid(TT / 64, HH, BB);           // (32, 16, 2)
        flash_attn_mma<<<grid, 128, AT_SMEM>>>(qp, ap);
    }
    // 3) out = attn @ Wout^T + bout (fp32)
    {
        dim3 grid(DD / 128, MROWS / 128);     // (8, 32)
        fp16_gemm_async<<<grid, 256, GK_SMEM>>>(ap, wo, bout,
                                                out, nullptr,
                                                MROWS, DD, DD, 0);
    }
}